// round 5
// baseline (speedup 1.0000x reference)
#include <cuda_runtime.h>
#include <cstdint>

// Problem constants (fixed by the reference)
#define HW      65536            // 256*256
#define BATCH   8
#define C0      128
#define NPIX    (BATCH * HW)     // 524288
#define THREADS 256
#define PX_PER_BLOCK 512
#define NBLOCKS (NPIX / PX_PER_BLOCK)   // 1024

// Shared-memory layout (float2 units).
// Weights: layer i stored as [c][o/2], element = {w[o][c], w[o+1][c]}.
#define OFF1 0        // 128 x 32 -> 4096
#define OFF2 4096     // 64 x 16  -> 1024
#define OFF3 5120     // 32 x 8   -> 256
#define OFF4 5376     // 16 x 4   -> 64
#define OFF5 5440     // 8 x 2    -> 16
#define OFF6 5456     // 4 x 1    -> 4
#define OFF7 5460     // 1        -> 1
// a0 buffer: [o2][px], o2 = 0..31 (channel pair), px = 0..511, f32x2 elements
#define A0_OFF 5464
#define A0_STRIDE 512
#define SMEM_F2_TOTAL (A0_OFF + 32 * A0_STRIDE)     // 21848
#define SMEM_BYTES (SMEM_F2_TOTAL * 8)              // 174784 bytes

__device__ __forceinline__ float2 ffma2(float2 a, float2 b, float2 c) {
    unsigned long long ra = reinterpret_cast<unsigned long long&>(a);
    unsigned long long rb = reinterpret_cast<unsigned long long&>(b);
    unsigned long long rc = reinterpret_cast<unsigned long long&>(c);
    unsigned long long rd;
    asm("fma.rn.f32x2 %0, %1, %2, %3;" : "=l"(rd) : "l"(ra), "l"(rb), "l"(rc));
    return reinterpret_cast<float2&>(rd);
}

__device__ __forceinline__ float2 leaky2(float2 v) {
    v.x = fmaxf(v.x, 0.01f * v.x);
    v.y = fmaxf(v.y, 0.01f * v.y);
    return v;
}

__device__ __forceinline__ void stage_pairs(float2* dst, const float* __restrict__ w,
                                            int cout, int cin, int tid) {
    int npair = (cout / 2) * cin;
    for (int i = tid; i < npair; i += THREADS) {
        int o2 = i / cin;
        int c  = i - o2 * cin;
        dst[c * (cout / 2) + o2] =
            make_float2(w[(2 * o2) * cin + c], w[(2 * o2 + 1) * cin + c]);
    }
}

// Dense layer for 2 pixels with output-pair packing. Fully unrolled (R3-proven).
template <int CIN, int COUT>
__device__ __forceinline__ void layer2px(const float2* __restrict__ sw,
                                         const float2* in0, const float2* in1,
                                         float2* acc0, float2* acc1) {
    constexpr int O2 = COUT / 2;
#pragma unroll
    for (int o = 0; o < O2; ++o) { acc0[o] = make_float2(0.f, 0.f); acc1[o] = make_float2(0.f, 0.f); }

#pragma unroll
    for (int c2 = 0; c2 < CIN / 2; ++c2) {
        float2 v0 = in0[c2];
        float2 v1 = in1[c2];
#pragma unroll
        for (int h = 0; h < 2; ++h) {
            float s0 = h ? v0.y : v0.x;
            float s1 = h ? v1.y : v1.x;
            float2 d0 = make_float2(s0, s0);
            float2 d1 = make_float2(s1, s1);
            const float2* wr = sw + (2 * c2 + h) * O2;
            if constexpr ((O2 & 1) == 0) {
                const float4* w4 = reinterpret_cast<const float4*>(wr);
#pragma unroll
                for (int o4 = 0; o4 < O2 / 2; ++o4) {
                    float4 wp = w4[o4];
                    float2 wa = make_float2(wp.x, wp.y);
                    float2 wb = make_float2(wp.z, wp.w);
                    acc0[2 * o4]     = ffma2(d0, wa, acc0[2 * o4]);
                    acc1[2 * o4]     = ffma2(d1, wa, acc1[2 * o4]);
                    acc0[2 * o4 + 1] = ffma2(d0, wb, acc0[2 * o4 + 1]);
                    acc1[2 * o4 + 1] = ffma2(d1, wb, acc1[2 * o4 + 1]);
                }
            } else {
#pragma unroll
                for (int o = 0; o < O2; ++o) {
                    float2 wp = wr[o];
                    acc0[o] = ffma2(d0, wp, acc0[o]);
                    acc1[o] = ffma2(d1, wp, acc1[o]);
                }
            }
        }
    }
}

__global__ __launch_bounds__(THREADS, 1)
void fused_mlp7_kernel(const float* __restrict__ x,
                       const float* __restrict__ w1, const float* __restrict__ w2,
                       const float* __restrict__ w3, const float* __restrict__ w4,
                       const float* __restrict__ w5, const float* __restrict__ w6,
                       const float* __restrict__ w7,
                       float* __restrict__ out) {
    extern __shared__ float2 sm[];
    float2* sw  = sm;
    float2* a0p = sm + A0_OFF;
    const int tid = threadIdx.x;

    stage_pairs(sw + OFF1, w1, 64, 128, tid);
    stage_pairs(sw + OFF2, w2, 32, 64, tid);
    stage_pairs(sw + OFF3, w3, 16, 32, tid);
    stage_pairs(sw + OFF4, w4, 8, 16, tid);
    stage_pairs(sw + OFF5, w5, 4, 8, tid);
    stage_pairs(sw + OFF6, w6, 2, 4, tid);
    if (tid == 0) sw[OFF7] = make_float2(w7[0], w7[1]);
    __syncthreads();

    const int wrp  = tid >> 5;
    const int lane = tid & 31;
    const int og   = wrp & 1;      // output group: o in [og*32, og*32+32)
    const int slb  = wrp >> 1;     // pixel slab: px in [slb*128, slb*128+128)
    const int blockBase = blockIdx.x * PX_PER_BLOCK;

    // ================= Layer 1: 128 -> 64 =================
    // Thread tile: 4 pixels (lane + {0,32,64,96} within slab) x 32 outputs (og).
    {
        const int pxl = slb * 128 + lane;            // local px base, +32*m
        const int g   = blockBase + pxl;
        const int b   = g >> 16;
        const int p   = g & (HW - 1);
        const float* xp = x + (size_t)b * (C0 * HW) + p;

        float2 acc[16][4];
#pragma unroll
        for (int j = 0; j < 16; ++j)
#pragma unroll
            for (int m = 0; m < 4; ++m) acc[j][m] = make_float2(0.f, 0.f);

        float xbuf[2][4];
#pragma unroll
        for (int m = 0; m < 4; ++m) {
            xbuf[0][m] = xp[(size_t)0 * HW + 32 * m];
            xbuf[1][m] = xp[(size_t)1 * HW + 32 * m];
        }

        const float2* wbase = sw + OFF1 + og * 16;   // + c*32

        for (int c = 0; c < 128; c += 2) {
            float cur[2][4];
#pragma unroll
            for (int h = 0; h < 2; ++h)
#pragma unroll
                for (int m = 0; m < 4; ++m) cur[h][m] = xbuf[h][m];

            if (c + 2 < 128) {
#pragma unroll
                for (int m = 0; m < 4; ++m) {
                    xbuf[0][m] = xp[(size_t)(c + 2) * HW + 32 * m];
                    xbuf[1][m] = xp[(size_t)(c + 3) * HW + 32 * m];
                }
            }

#pragma unroll
            for (int h = 0; h < 2; ++h) {
                float2 d[4];
#pragma unroll
                for (int m = 0; m < 4; ++m) d[m] = make_float2(cur[h][m], cur[h][m]);
                const float4* w4 = reinterpret_cast<const float4*>(wbase + (size_t)(c + h) * 32);
#pragma unroll
                for (int j4 = 0; j4 < 8; ++j4) {
                    float4 wq = w4[j4];
                    float2 wa = make_float2(wq.x, wq.y);
                    float2 wb = make_float2(wq.z, wq.w);
#pragma unroll
                    for (int m = 0; m < 4; ++m) {
                        acc[2 * j4][m]     = ffma2(d[m], wa, acc[2 * j4][m]);
                        acc[2 * j4 + 1][m] = ffma2(d[m], wb, acc[2 * j4 + 1][m]);
                    }
                }
            }
        }

        // Leaky + store to a0p[o2][px]: lanes contiguous 8B -> conflict-free.
#pragma unroll
        for (int j = 0; j < 16; ++j) {
            float2* row = a0p + (size_t)(og * 16 + j) * A0_STRIDE + pxl;
#pragma unroll
            for (int m = 0; m < 4; ++m) row[32 * m] = leaky2(acc[j][m]);
        }
    }
    __syncthreads();

    // ================= Layers 2..7: 2 px/thread (px0 = tid, px1 = tid+256) =================
    float2 a0_0[32], a0_1[32];
#pragma unroll
    for (int c2 = 0; c2 < 32; ++c2) {
        a0_0[c2] = a0p[(size_t)c2 * A0_STRIDE + tid];
        a0_1[c2] = a0p[(size_t)c2 * A0_STRIDE + tid + 256];
    }

    float2 a1_0[16], a1_1[16];
    layer2px<64, 32>(sw + OFF2, a0_0, a0_1, a1_0, a1_1);
#pragma unroll
    for (int o = 0; o < 16; ++o) { a1_0[o] = leaky2(a1_0[o]); a1_1[o] = leaky2(a1_1[o]); }

    float2 a2_0[8], a2_1[8];
    layer2px<32, 16>(sw + OFF3, a1_0, a1_1, a2_0, a2_1);
#pragma unroll
    for (int o = 0; o < 8; ++o) { a2_0[o] = leaky2(a2_0[o]); a2_1[o] = leaky2(a2_1[o]); }

    float2 a3_0[4], a3_1[4];
    layer2px<16, 8>(sw + OFF4, a2_0, a2_1, a3_0, a3_1);
#pragma unroll
    for (int o = 0; o < 4; ++o) { a3_0[o] = leaky2(a3_0[o]); a3_1[o] = leaky2(a3_1[o]); }

    float2 a4_0[2], a4_1[2];
    layer2px<8, 4>(sw + OFF5, a3_0, a3_1, a4_0, a4_1);
#pragma unroll
    for (int o = 0; o < 2; ++o) { a4_0[o] = leaky2(a4_0[o]); a4_1[o] = leaky2(a4_1[o]); }

    float2 a5_0[1], a5_1[1];
    layer2px<4, 2>(sw + OFF6, a4_0, a4_1, a5_0, a5_1);
    a5_0[0] = leaky2(a5_0[0]);
    a5_1[0] = leaky2(a5_1[0]);

    float2 w7p = sw[OFF7];
    float r0 = fmaf(a5_0[0].x, w7p.x, a5_0[0].y * w7p.y);
    float r1 = fmaf(a5_1[0].x, w7p.x, a5_1[0].y * w7p.y);

    const int g0 = blockBase + tid;
    out[g0]       = r0;
    out[g0 + 256] = r1;
}

extern "C" void kernel_launch(void* const* d_in, const int* in_sizes, int n_in,
                              void* d_out, int out_size) {
    const float* x  = (const float*)d_in[0];
    const float* w1 = (const float*)d_in[1];
    const float* w2 = (const float*)d_in[2];
    const float* w3 = (const float*)d_in[3];
    const float* w4 = (const float*)d_in[4];
    const float* w5 = (const float*)d_in[5];
    const float* w6 = (const float*)d_in[6];
    const float* w7 = (const float*)d_in[7];
    float* out = (float*)d_out;

    cudaFuncSetAttribute(fused_mlp7_kernel,
                         cudaFuncAttributeMaxDynamicSharedMemorySize, SMEM_BYTES);
    fused_mlp7_kernel<<<NBLOCKS, THREADS, SMEM_BYTES>>>(x, w1, w2, w3, w4, w5, w6, w7, out);
}

// round 7
// speedup vs baseline: 1.7241x; 1.7241x over previous
#include <cuda_runtime.h>
#include <cuda_bf16.h>
#include <cstdint>

#define HW      65536
#define NPIX    524288
#define THREADS 256
#define PX_CTA  512
#define NCTAS   (NPIX / PX_CTA)   // 1024

// ---- dynamic smem byte layout ----
#define SW_OFF  0          // float2[1365] pair-packed w2..w7 = 10920 B
#define B_OFF   10944      // w1 bf16 hi/lo: 2 * 64*272 = 34816 -> ends 45760
#define A_OFF   45760      // x tile bf16 hi/lo: 2 * 512*48 = 49152 -> ends 94912
#define A0_OFF  45760      // layer-1 output f32: 512*272 = 139264 (overlaps A; used after MMA) -> ends 185024
#define SMEM_TOTAL 185024

#define A_PITCH 48
#define A_SPLIT 24576
#define B_PITCH 272
#define B_SPLIT 17408
#define A0_PITCH 272

// pair-packed weight offsets inside s_w (float2 units)
#define W2OFF 0
#define W3OFF 1024
#define W4OFF 1280
#define W5OFF 1344
#define W6OFF 1360
#define W7OFF 1364

__device__ __forceinline__ uint32_t smem_u32(const void* p) {
    uint32_t a;
    asm("{ .reg .u64 t; cvta.to.shared.u64 t, %1; cvt.u32.u64 %0, t; }" : "=r"(a) : "l"(p));
    return a;
}
__device__ __forceinline__ float2 ffma2(float2 a, float2 b, float2 c) {
    unsigned long long ra = reinterpret_cast<unsigned long long&>(a);
    unsigned long long rb = reinterpret_cast<unsigned long long&>(b);
    unsigned long long rc = reinterpret_cast<unsigned long long&>(c);
    unsigned long long rd;
    asm("fma.rn.f32x2 %0, %1, %2, %3;" : "=l"(rd) : "l"(ra), "l"(rb), "l"(rc));
    return reinterpret_cast<float2&>(rd);
}
__device__ __forceinline__ float2 leaky2(float2 v) {
    v.x = fmaxf(v.x, 0.01f * v.x);
    v.y = fmaxf(v.y, 0.01f * v.y);
    return v;
}

__device__ __forceinline__ void ldmx4(uint32_t* r, uint32_t addr) {
    asm volatile("ldmatrix.sync.aligned.m8n8.x4.shared.b16 {%0,%1,%2,%3}, [%4];"
                 : "=r"(r[0]), "=r"(r[1]), "=r"(r[2]), "=r"(r[3]) : "r"(addr));
}
__device__ __forceinline__ void mma16816(float* d, const uint32_t* a, uint32_t b0, uint32_t b1) {
    asm volatile("mma.sync.aligned.m16n8k16.row.col.f32.bf16.bf16.f32 "
                 "{%0,%1,%2,%3}, {%4,%5,%6,%7}, {%8,%9}, {%0,%1,%2,%3};"
                 : "+f"(d[0]), "+f"(d[1]), "+f"(d[2]), "+f"(d[3])
                 : "r"(a[0]), "r"(a[1]), "r"(a[2]), "r"(a[3]), "r"(b0), "r"(b1));
}

// split f32 pair -> bf16x2 hi + bf16x2 lo
__device__ __forceinline__ void cvt_hilo(float a, float b, uint32_t& hi, uint32_t& lo) {
    __nv_bfloat162 h2 = __floats2bfloat162_rn(a, b);
    float2 hf = __bfloat1622float2(h2);
    __nv_bfloat162 l2 = __floats2bfloat162_rn(a - hf.x, b - hf.y);
    hi = reinterpret_cast<uint32_t&>(h2);
    lo = reinterpret_cast<uint32_t&>(l2);
}

__device__ __forceinline__ void stage_pairs(float2* dst, const float* __restrict__ w,
                                            int cout, int cin, int tid) {
    int npair = (cout / 2) * cin;
    for (int i = tid; i < npair; i += THREADS) {
        int o2 = i / cin;
        int c  = i - o2 * cin;
        dst[c * (cout / 2) + o2] = make_float2(w[(2 * o2) * cin + c], w[(2 * o2 + 1) * cin + c]);
    }
}

// R3-proven scalar layer for 2 pixels, channel-pair packed.
template <int CIN, int COUT>
__device__ __forceinline__ void layer2px(const float2* __restrict__ sw,
                                         const float2* in0, const float2* in1,
                                         float2* acc0, float2* acc1) {
    constexpr int O2 = COUT / 2;
#pragma unroll
    for (int o = 0; o < O2; ++o) { acc0[o] = make_float2(0.f, 0.f); acc1[o] = make_float2(0.f, 0.f); }
#pragma unroll
    for (int c2 = 0; c2 < CIN / 2; ++c2) {
        float2 v0 = in0[c2];
        float2 v1 = in1[c2];
#pragma unroll
        for (int h = 0; h < 2; ++h) {
            float s0 = h ? v0.y : v0.x;
            float s1 = h ? v1.y : v1.x;
            float2 d0 = make_float2(s0, s0);
            float2 d1 = make_float2(s1, s1);
            const float2* wr = sw + (2 * c2 + h) * O2;
            if constexpr ((O2 & 1) == 0) {
                const float4* w4 = reinterpret_cast<const float4*>(wr);
#pragma unroll
                for (int o4 = 0; o4 < O2 / 2; ++o4) {
                    float4 wp = w4[o4];
                    acc0[2 * o4]     = ffma2(d0, make_float2(wp.x, wp.y), acc0[2 * o4]);
                    acc1[2 * o4]     = ffma2(d1, make_float2(wp.x, wp.y), acc1[2 * o4]);
                    acc0[2 * o4 + 1] = ffma2(d0, make_float2(wp.z, wp.w), acc0[2 * o4 + 1]);
                    acc1[2 * o4 + 1] = ffma2(d1, make_float2(wp.z, wp.w), acc1[2 * o4 + 1]);
                }
            } else {
#pragma unroll
                for (int o = 0; o < O2; ++o) {
                    float2 wp = wr[o];
                    acc0[o] = ffma2(d0, wp, acc0[o]);
                    acc1[o] = ffma2(d1, wp, acc1[o]);
                }
            }
        }
    }
}

__global__ __launch_bounds__(THREADS, 1)
void fused_mlp7_hmma_kernel(const float* __restrict__ x,
                            const float* __restrict__ w1, const float* __restrict__ w2,
                            const float* __restrict__ w3, const float* __restrict__ w4,
                            const float* __restrict__ w5, const float* __restrict__ w6,
                            const float* __restrict__ w7,
                            float* __restrict__ out) {
    extern __shared__ char sm[];
    float2* s_w = reinterpret_cast<float2*>(sm + SW_OFF);

    const int tid  = threadIdx.x;
    const int lane = tid & 31;
    const int warp = tid >> 5;

    const uint32_t smu = smem_u32(sm);
    const uint32_t Bh  = smu + B_OFF;
    const uint32_t Ahs = smu + A_OFF;

    // ---- stage w1 as bf16 hi/lo, [o][c], 272B pitch ----
    for (int i = tid; i < 64 * 128; i += THREADS) {
        int o = i >> 7, c = i & 127;
        float f = w1[i];
        __nv_bfloat16 h = __float2bfloat16_rn(f);
        __nv_bfloat16 l = __float2bfloat16_rn(f - __bfloat162float(h));
        char* ad = sm + B_OFF + o * B_PITCH + c * 2;
        *reinterpret_cast<uint16_t*>(ad)           = reinterpret_cast<uint16_t&>(h);
        *reinterpret_cast<uint16_t*>(ad + B_SPLIT) = reinterpret_cast<uint16_t&>(l);
    }
    stage_pairs(s_w + W2OFF, w2, 32, 64, tid);
    stage_pairs(s_w + W3OFF, w3, 16, 32, tid);
    stage_pairs(s_w + W4OFF, w4, 8, 16, tid);
    stage_pairs(s_w + W5OFF, w5, 4, 8, tid);
    stage_pairs(s_w + W6OFF, w6, 2, 4, tid);
    if (tid == 0) s_w[W7OFF] = make_float2(w7[0], w7[1]);

    // ---- pixel pointers (px0 = tid, px1 = tid + 256; block never straddles images) ----
    const int g0 = blockIdx.x * PX_CTA + tid;
    const int g1 = g0 + 256;
    const float* xp0 = x + (size_t)(g0 >> 16) * (128 * HW) + (g0 & (HW - 1));
    const float* xp1 = x + (size_t)(g1 >> 16) * (128 * HW) + (g1 & (HW - 1));

    // ---- accumulators: warp tile 64px x 64o ----
    float acc[4][8][4];
#pragma unroll
    for (int mb = 0; mb < 4; ++mb)
#pragma unroll
        for (int nb = 0; nb < 8; ++nb)
#pragma unroll
            for (int r = 0; r < 4; ++r) acc[mb][nb][r] = 0.f;

    const int pxw = warp * 64;
    // ldmatrix lane -> (row, chunk) mapping shared by A and B
    const int lrow = (lane & 7) + ((lane >> 3) & 1) * 8;
    const int lchk = lane >> 4;

    for (int kb = 0; kb < 8; ++kb) {
        // load next x slice (LDG latency overlaps previous MMA phase)
        float f0[16], f1[16];
#pragma unroll
        for (int i = 0; i < 16; ++i) {
            f0[i] = xp0[(size_t)(kb * 16 + i) * HW];
            f1[i] = xp1[(size_t)(kb * 16 + i) * HW];
        }
        __syncthreads();   // previous step's A tile fully consumed (ldmatrix done before mma issue)

        // convert + store both pixels' rows (hi & lo tiles)
        {
            uint32_t h[8], l[8];
#pragma unroll
            for (int j = 0; j < 8; ++j) cvt_hilo(f0[2 * j], f0[2 * j + 1], h[j], l[j]);
            char* r0 = sm + A_OFF + tid * A_PITCH;
            *reinterpret_cast<uint4*>(r0)      = make_uint4(h[0], h[1], h[2], h[3]);
            *reinterpret_cast<uint4*>(r0 + 16) = make_uint4(h[4], h[5], h[6], h[7]);
            *reinterpret_cast<uint4*>(r0 + A_SPLIT)      = make_uint4(l[0], l[1], l[2], l[3]);
            *reinterpret_cast<uint4*>(r0 + A_SPLIT + 16) = make_uint4(l[4], l[5], l[6], l[7]);
#pragma unroll
            for (int j = 0; j < 8; ++j) cvt_hilo(f1[2 * j], f1[2 * j + 1], h[j], l[j]);
            char* r1 = sm + A_OFF + (tid + 256) * A_PITCH;
            *reinterpret_cast<uint4*>(r1)      = make_uint4(h[0], h[1], h[2], h[3]);
            *reinterpret_cast<uint4*>(r1 + 16) = make_uint4(h[4], h[5], h[6], h[7]);
            *reinterpret_cast<uint4*>(r1 + A_SPLIT)      = make_uint4(l[0], l[1], l[2], l[3]);
            *reinterpret_cast<uint4*>(r1 + A_SPLIT + 16) = make_uint4(l[4], l[5], l[6], l[7]);
        }
        __syncthreads();   // A tile ready

        // ---- fragments ----
        uint32_t AH[4][4], AL[4][4], BHf[4][4], BLf[4][4];
#pragma unroll
        for (int mb = 0; mb < 4; ++mb) {
            uint32_t ad = Ahs + (uint32_t)(pxw + mb * 16 + lrow) * A_PITCH + lchk * 16;
            ldmx4(AH[mb], ad);
            ldmx4(AL[mb], ad + A_SPLIT);
        }
#pragma unroll
        for (int p = 0; p < 4; ++p) {
            uint32_t bd = Bh + (uint32_t)(p * 16 + lrow) * B_PITCH + kb * 32 + lchk * 16;
            ldmx4(BHf[p], bd);
            ldmx4(BLf[p], bd + B_SPLIT);
        }

        // ---- MMA: 3 chains, independent tiles inside each pass ----
#pragma unroll
        for (int mb = 0; mb < 4; ++mb)
#pragma unroll
            for (int p = 0; p < 4; ++p) {
                mma16816(acc[mb][2 * p],     AH[mb], BHf[p][0], BHf[p][2]);
                mma16816(acc[mb][2 * p + 1], AH[mb], BHf[p][1], BHf[p][3]);
            }
#pragma unroll
        for (int mb = 0; mb < 4; ++mb)
#pragma unroll
            for (int p = 0; p < 4; ++p) {
                mma16816(acc[mb][2 * p],     AL[mb], BHf[p][0], BHf[p][2]);
                mma16816(acc[mb][2 * p + 1], AL[mb], BHf[p][1], BHf[p][3]);
            }
#pragma unroll
        for (int mb = 0; mb < 4; ++mb)
#pragma unroll
            for (int p = 0; p < 4; ++p) {
                mma16816(acc[mb][2 * p],     AH[mb], BLf[p][0], BLf[p][2]);
                mma16816(acc[mb][2 * p + 1], AH[mb], BLf[p][1], BLf[p][3]);
            }
    }

    __syncthreads();   // all ldmatrix of last step done -> A region reusable as a0

    // ---- D fragments -> leaky -> a0[px][o] (272B pitch) ----
    {
        const int qr = lane >> 2, qc = lane & 3;
#pragma unroll
        for (int mb = 0; mb < 4; ++mb) {
            int px = pxw + mb * 16 + qr;
            char* row0 = sm + A0_OFF + (size_t)px * A0_PITCH;
            char* row1 = row0 + 8 * A0_PITCH;
#pragma unroll
            for (int nb = 0; nb < 8; ++nb) {
                int cb = (nb * 8 + qc * 2) * 4;
                *reinterpret_cast<float2*>(row0 + cb) =
                    leaky2(make_float2(acc[mb][nb][0], acc[mb][nb][1]));
                *reinterpret_cast<float2*>(row1 + cb) =
                    leaky2(make_float2(acc[mb][nb][2], acc[mb][nb][3]));
            }
        }
    }
    __syncthreads();

    // ---- layers 2..7, 2 px/thread, R3 scalar chain ----
    float2 a0_0[32], a0_1[32];
    {
        const float4* r0 = reinterpret_cast<const float4*>(sm + A0_OFF + (size_t)tid * A0_PITCH);
        const float4* r1 = reinterpret_cast<const float4*>(sm + A0_OFF + (size_t)(tid + 256) * A0_PITCH);
#pragma unroll
        for (int j = 0; j < 16; ++j) {
            float4 q0 = r0[j], q1 = r1[j];
            a0_0[2 * j]     = make_float2(q0.x, q0.y);
            a0_0[2 * j + 1] = make_float2(q0.z, q0.w);
            a0_1[2 * j]     = make_float2(q1.x, q1.y);
            a0_1[2 * j + 1] = make_float2(q1.z, q1.w);
        }
    }

    float2 a1_0[16], a1_1[16];
    layer2px<64, 32>(s_w + W2OFF, a0_0, a0_1, a1_0, a1_1);
#pragma unroll
    for (int o = 0; o < 16; ++o) { a1_0[o] = leaky2(a1_0[o]); a1_1[o] = leaky2(a1_1[o]); }

    float2 a2_0[8], a2_1[8];
    layer2px<32, 16>(s_w + W3OFF, a1_0, a1_1, a2_0, a2_1);
#pragma unroll
    for (int o = 0; o < 8; ++o) { a2_0[o] = leaky2(a2_0[o]); a2_1[o] = leaky2(a2_1[o]); }

    float2 a3_0[4], a3_1[4];
    layer2px<16, 8>(s_w + W4OFF, a2_0, a2_1, a3_0, a3_1);
#pragma unroll
    for (int o = 0; o < 4; ++o) { a3_0[o] = leaky2(a3_0[o]); a3_1[o] = leaky2(a3_1[o]); }

    float2 a4_0[2], a4_1[2];
    layer2px<8, 4>(s_w + W5OFF, a3_0, a3_1, a4_0, a4_1);
#pragma unroll
    for (int o = 0; o < 2; ++o) { a4_0[o] = leaky2(a4_0[o]); a4_1[o] = leaky2(a4_1[o]); }

    float2 a5_0[1], a5_1[1];
    layer2px<4, 2>(s_w + W6OFF, a4_0, a4_1, a5_0, a5_1);
    a5_0[0] = leaky2(a5_0[0]);
    a5_1[0] = leaky2(a5_1[0]);

    float2 w7p = s_w[W7OFF];
    out[g0] = fmaf(a5_0[0].x, w7p.x, a5_0[0].y * w7p.y);
    out[g1] = fmaf(a5_1[0].x, w7p.x, a5_1[0].y * w7p.y);
}

extern "C" void kernel_launch(void* const* d_in, const int* in_sizes, int n_in,
                              void* d_out, int out_size) {
    const float* x  = (const float*)d_in[0];
    const float* w1 = (const float*)d_in[1];
    const float* w2 = (const float*)d_in[2];
    const float* w3 = (const float*)d_in[3];
    const float* w4 = (const float*)d_in[4];
    const float* w5 = (const float*)d_in[5];
    const float* w6 = (const float*)d_in[6];
    const float* w7 = (const float*)d_in[7];
    float* out = (float*)d_out;

    cudaFuncSetAttribute(fused_mlp7_hmma_kernel,
                         cudaFuncAttributeMaxDynamicSharedMemorySize, SMEM_TOTAL);
    fused_mlp7_hmma_kernel<<<NCTAS, THREADS, SMEM_TOTAL>>>(x, w1, w2, w3, w4, w5, w6, w7, out);
}

// round 8
// speedup vs baseline: 2.0121x; 1.1670x over previous
#include <cuda_runtime.h>
#include <cuda_bf16.h>
#include <cstdint>

#define HW      65536
#define NPIX    524288
#define THREADS 256
#define PX_CTA  512
#define NCTAS   (NPIX / PX_CTA)   // 1024

// ---- dynamic smem byte layout ----
#define SW_OFF  0          // float2[1365] pair-packed w2..w7 = 10920 B
#define B_OFF   10944      // w1 bf16 hi/lo: 2 * 64*272 = 34816 -> ends 45760
#define A0_OFF  45760      // layer-1 output f32: 512*272 = 139264 -> ends 185024
#define SMEM_TOTAL 185024

#define B_PITCH 272
#define B_SPLIT 17408
#define A0_PITCH 272

// pair-packed weight offsets inside s_w (float2 units)
#define W2OFF 0
#define W3OFF 1024
#define W4OFF 1280
#define W5OFF 1344
#define W6OFF 1360
#define W7OFF 1364

__device__ __forceinline__ uint32_t smem_u32(const void* p) {
    uint32_t a;
    asm("{ .reg .u64 t; cvta.to.shared.u64 t, %1; cvt.u32.u64 %0, t; }" : "=r"(a) : "l"(p));
    return a;
}
__device__ __forceinline__ float2 ffma2(float2 a, float2 b, float2 c) {
    unsigned long long ra = reinterpret_cast<unsigned long long&>(a);
    unsigned long long rb = reinterpret_cast<unsigned long long&>(b);
    unsigned long long rc = reinterpret_cast<unsigned long long&>(c);
    unsigned long long rd;
    asm("fma.rn.f32x2 %0, %1, %2, %3;" : "=l"(rd) : "l"(ra), "l"(rb), "l"(rc));
    return reinterpret_cast<float2&>(rd);
}
__device__ __forceinline__ float2 leaky2(float2 v) {
    v.x = fmaxf(v.x, 0.01f * v.x);
    v.y = fmaxf(v.y, 0.01f * v.y);
    return v;
}
__device__ __forceinline__ void ldmx4(uint32_t* r, uint32_t addr) {
    asm volatile("ldmatrix.sync.aligned.m8n8.x4.shared.b16 {%0,%1,%2,%3}, [%4];"
                 : "=r"(r[0]), "=r"(r[1]), "=r"(r[2]), "=r"(r[3]) : "r"(addr));
}
__device__ __forceinline__ void mma16816(float* d, const uint32_t* a, uint32_t b0, uint32_t b1) {
    asm volatile("mma.sync.aligned.m16n8k16.row.col.f32.bf16.bf16.f32 "
                 "{%0,%1,%2,%3}, {%4,%5,%6,%7}, {%8,%9}, {%0,%1,%2,%3};"
                 : "+f"(d[0]), "+f"(d[1]), "+f"(d[2]), "+f"(d[3])
                 : "r"(a[0]), "r"(a[1]), "r"(a[2]), "r"(a[3]), "r"(b0), "r"(b1));
}
// split f32 pair -> bf16x2 hi + bf16x2 lo
__device__ __forceinline__ void cvt_hilo(float a, float b, uint32_t& hi, uint32_t& lo) {
    __nv_bfloat162 h2 = __floats2bfloat162_rn(a, b);
    float2 hf = __bfloat1622float2(h2);
    __nv_bfloat162 l2 = __floats2bfloat162_rn(a - hf.x, b - hf.y);
    hi = reinterpret_cast<uint32_t&>(h2);
    lo = reinterpret_cast<uint32_t&>(l2);
}

__device__ __forceinline__ void stage_pairs(float2* dst, const float* __restrict__ w,
                                            int cout, int cin, int tid) {
    int npair = (cout / 2) * cin;
    for (int i = tid; i < npair; i += THREADS) {
        int o2 = i / cin;
        int c  = i - o2 * cin;
        dst[c * (cout / 2) + o2] = make_float2(w[(2 * o2) * cin + c], w[(2 * o2 + 1) * cin + c]);
    }
}

// R3-proven scalar layer for 2 pixels, channel-pair packed.
template <int CIN, int COUT>
__device__ __forceinline__ void layer2px(const float2* __restrict__ sw,
                                         const float2* in0, const float2* in1,
                                         float2* acc0, float2* acc1) {
    constexpr int O2 = COUT / 2;
#pragma unroll
    for (int o = 0; o < O2; ++o) { acc0[o] = make_float2(0.f, 0.f); acc1[o] = make_float2(0.f, 0.f); }
#pragma unroll
    for (int c2 = 0; c2 < CIN / 2; ++c2) {
        float2 v0 = in0[c2];
        float2 v1 = in1[c2];
#pragma unroll
        for (int h = 0; h < 2; ++h) {
            float s0 = h ? v0.y : v0.x;
            float s1 = h ? v1.y : v1.x;
            float2 d0 = make_float2(s0, s0);
            float2 d1 = make_float2(s1, s1);
            const float2* wr = sw + (2 * c2 + h) * O2;
            if constexpr ((O2 & 1) == 0) {
                const float4* w4 = reinterpret_cast<const float4*>(wr);
#pragma unroll
                for (int o4 = 0; o4 < O2 / 2; ++o4) {
                    float4 wp = w4[o4];
                    acc0[2 * o4]     = ffma2(d0, make_float2(wp.x, wp.y), acc0[2 * o4]);
                    acc1[2 * o4]     = ffma2(d1, make_float2(wp.x, wp.y), acc1[2 * o4]);
                    acc0[2 * o4 + 1] = ffma2(d0, make_float2(wp.z, wp.w), acc0[2 * o4 + 1]);
                    acc1[2 * o4 + 1] = ffma2(d1, make_float2(wp.z, wp.w), acc1[2 * o4 + 1]);
                }
            } else {
#pragma unroll
                for (int o = 0; o < O2; ++o) {
                    float2 wp = wr[o];
                    acc0[o] = ffma2(d0, wp, acc0[o]);
                    acc1[o] = ffma2(d1, wp, acc1[o]);
                }
            }
        }
    }
}

__global__ __launch_bounds__(THREADS, 1)
void fused_mlp7_hmma_kernel(const float* __restrict__ x,
                            const float* __restrict__ w1, const float* __restrict__ w2,
                            const float* __restrict__ w3, const float* __restrict__ w4,
                            const float* __restrict__ w5, const float* __restrict__ w6,
                            const float* __restrict__ w7,
                            float* __restrict__ out) {
    extern __shared__ char sm[];
    float2* s_w = reinterpret_cast<float2*>(sm + SW_OFF);

    const int tid  = threadIdx.x;
    const int lane = tid & 31;
    const int warp = tid >> 5;

    const uint32_t smu = smem_u32(sm);
    const uint32_t Bh  = smu + B_OFF;

    // ---- stage w1 as bf16 hi/lo, [o][c], 272B pitch ----
    for (int i = tid; i < 64 * 128; i += THREADS) {
        int o = i >> 7, c = i & 127;
        float f = w1[i];
        __nv_bfloat16 h = __float2bfloat16_rn(f);
        __nv_bfloat16 l = __float2bfloat16_rn(f - __bfloat162float(h));
        char* ad = sm + B_OFF + o * B_PITCH + c * 2;
        *reinterpret_cast<uint16_t*>(ad)           = reinterpret_cast<uint16_t&>(h);
        *reinterpret_cast<uint16_t*>(ad + B_SPLIT) = reinterpret_cast<uint16_t&>(l);
    }
    stage_pairs(s_w + W2OFF, w2, 32, 64, tid);
    stage_pairs(s_w + W3OFF, w3, 16, 32, tid);
    stage_pairs(s_w + W4OFF, w4, 8, 16, tid);
    stage_pairs(s_w + W5OFF, w5, 4, 8, tid);
    stage_pairs(s_w + W6OFF, w6, 2, 4, tid);
    if (tid == 0) s_w[W7OFF] = make_float2(w7[0], w7[1]);
    __syncthreads();   // B + s_w ready; no more barriers until epilogue

    // ---- base pointer for this CTA's 512-px slab (whole block in one image) ----
    const int slab = blockIdx.x * PX_CTA;
    const float* xb = x + (size_t)(slab >> 16) * (128 * HW) + (slab & (HW - 1));

    // fragment coords
    const int fg = lane >> 2;          // 0..7 (px row within 8)
    const int t2 = (lane & 3) * 2;     // col pair base
    const int pxw = warp * 64;
    const int lrow = (lane & 7) + ((lane >> 3) & 1) * 8;   // ldmatrix row (B)
    const int lchk = lane >> 4;

    // per-lane global load base: pl0 = pxw + mb*16 + fg, c = kb*16 + t2 + {0,1,8,9}
    float acc[4][8][4];
#pragma unroll
    for (int mb = 0; mb < 4; ++mb)
#pragma unroll
        for (int nb = 0; nb < 8; ++nb)
#pragma unroll
            for (int r = 0; r < 4; ++r) acc[mb][nb][r] = 0.f;

    // x register buffer: xr[mb][8] = {(g,c0),(g,c0+1),(g+8,c0),(g+8,c0+1),(g,c0+8),(g,c0+9),(g+8,c0+8),(g+8,c0+9)}
    float xr[4][8];
#define LOAD_XR(kb_)                                                              \
    do {                                                                          \
        const float* cb0 = xb + (size_t)((kb_) * 16 + t2) * HW;                   \
        const float* cb1 = cb0 + HW;                                              \
        const float* cb8 = cb0 + (size_t)8 * HW;                                  \
        const float* cb9 = cb8 + HW;                                              \
        _Pragma("unroll")                                                         \
        for (int mb = 0; mb < 4; ++mb) {                                          \
            int p0 = pxw + mb * 16 + fg;                                          \
            xr[mb][0] = cb0[p0];     xr[mb][1] = cb1[p0];                         \
            xr[mb][2] = cb0[p0 + 8]; xr[mb][3] = cb1[p0 + 8];                     \
            xr[mb][4] = cb8[p0];     xr[mb][5] = cb9[p0];                         \
            xr[mb][6] = cb8[p0 + 8]; xr[mb][7] = cb9[p0 + 8];                     \
        }                                                                         \
    } while (0)

    LOAD_XR(0);

#pragma unroll
    for (int kb = 0; kb < 8; ++kb) {
        // convert current buffer -> A fragments (frees xr)
        uint32_t AH[4][4], AL[4][4];
#pragma unroll
        for (int mb = 0; mb < 4; ++mb) {
            cvt_hilo(xr[mb][0], xr[mb][1], AH[mb][0], AL[mb][0]);
            cvt_hilo(xr[mb][2], xr[mb][3], AH[mb][1], AL[mb][1]);
            cvt_hilo(xr[mb][4], xr[mb][5], AH[mb][2], AL[mb][2]);
            cvt_hilo(xr[mb][6], xr[mb][7], AH[mb][3], AL[mb][3]);
        }
        // prefetch next k-step (latency covered by ldmatrix + mma below)
        if (kb < 7) LOAD_XR(kb + 1);

        // B fragments for this k-step
        uint32_t BHf[4][4], BLf[4][4];
#pragma unroll
        for (int p = 0; p < 4; ++p) {
            uint32_t bd = Bh + (uint32_t)(p * 16 + lrow) * B_PITCH + kb * 32 + lchk * 16;
            ldmx4(BHf[p], bd);
            ldmx4(BLf[p], bd + B_SPLIT);
        }

        // 3 chains: AhiBhi + AloBhi + AhiBlo
#pragma unroll
        for (int mb = 0; mb < 4; ++mb)
#pragma unroll
            for (int p = 0; p < 4; ++p) {
                mma16816(acc[mb][2 * p],     AH[mb], BHf[p][0], BHf[p][2]);
                mma16816(acc[mb][2 * p + 1], AH[mb], BHf[p][1], BHf[p][3]);
            }
#pragma unroll
        for (int mb = 0; mb < 4; ++mb)
#pragma unroll
            for (int p = 0; p < 4; ++p) {
                mma16816(acc[mb][2 * p],     AL[mb], BHf[p][0], BHf[p][2]);
                mma16816(acc[mb][2 * p + 1], AL[mb], BHf[p][1], BHf[p][3]);
            }
#pragma unroll
        for (int mb = 0; mb < 4; ++mb)
#pragma unroll
            for (int p = 0; p < 4; ++p) {
                mma16816(acc[mb][2 * p],     AH[mb], BLf[p][0], BLf[p][2]);
                mma16816(acc[mb][2 * p + 1], AH[mb], BLf[p][1], BLf[p][3]);
            }
    }
#undef LOAD_XR

    // ---- D fragments -> leaky -> a0[px][o] (272B pitch) ----
    {
        const int qr = lane >> 2, qc = lane & 3;
#pragma unroll
        for (int mb = 0; mb < 4; ++mb) {
            int px = pxw + mb * 16 + qr;
            char* row0 = sm + A0_OFF + (size_t)px * A0_PITCH;
            char* row1 = row0 + 8 * A0_PITCH;
#pragma unroll
            for (int nb = 0; nb < 8; ++nb) {
                int cb = (nb * 8 + qc * 2) * 4;
                *reinterpret_cast<float2*>(row0 + cb) =
                    leaky2(make_float2(acc[mb][nb][0], acc[mb][nb][1]));
                *reinterpret_cast<float2*>(row1 + cb) =
                    leaky2(make_float2(acc[mb][nb][2], acc[mb][nb][3]));
            }
        }
    }
    __syncthreads();

    // ---- layers 2..7, 2 px/thread, R3 scalar chain ----
    float2 a0_0[32], a0_1[32];
    {
        const float4* r0 = reinterpret_cast<const float4*>(sm + A0_OFF + (size_t)tid * A0_PITCH);
        const float4* r1 = reinterpret_cast<const float4*>(sm + A0_OFF + (size_t)(tid + 256) * A0_PITCH);
#pragma unroll
        for (int j = 0; j < 16; ++j) {
            float4 q0 = r0[j], q1 = r1[j];
            a0_0[2 * j]     = make_float2(q0.x, q0.y);
            a0_0[2 * j + 1] = make_float2(q0.z, q0.w);
            a0_1[2 * j]     = make_float2(q1.x, q1.y);
            a0_1[2 * j + 1] = make_float2(q1.z, q1.w);
        }
    }

    float2 a1_0[16], a1_1[16];
    layer2px<64, 32>(s_w + W2OFF, a0_0, a0_1, a1_0, a1_1);
#pragma unroll
    for (int o = 0; o < 16; ++o) { a1_0[o] = leaky2(a1_0[o]); a1_1[o] = leaky2(a1_1[o]); }

    float2 a2_0[8], a2_1[8];
    layer2px<32, 16>(s_w + W3OFF, a1_0, a1_1, a2_0, a2_1);
#pragma unroll
    for (int o = 0; o < 8; ++o) { a2_0[o] = leaky2(a2_0[o]); a2_1[o] = leaky2(a2_1[o]); }

    float2 a3_0[4], a3_1[4];
    layer2px<16, 8>(s_w + W4OFF, a2_0, a2_1, a3_0, a3_1);
#pragma unroll
    for (int o = 0; o < 4; ++o) { a3_0[o] = leaky2(a3_0[o]); a3_1[o] = leaky2(a3_1[o]); }

    float2 a4_0[2], a4_1[2];
    layer2px<8, 4>(s_w + W5OFF, a3_0, a3_1, a4_0, a4_1);
#pragma unroll
    for (int o = 0; o < 2; ++o) { a4_0[o] = leaky2(a4_0[o]); a4_1[o] = leaky2(a4_1[o]); }

    float2 a5_0[1], a5_1[1];
    layer2px<4, 2>(s_w + W6OFF, a4_0, a4_1, a5_0, a5_1);
    a5_0[0] = leaky2(a5_0[0]);
    a5_1[0] = leaky2(a5_1[0]);

    float2 w7p = s_w[W7OFF];
    const int g0 = slab + tid;
    out[g0]       = fmaf(a5_0[0].x, w7p.x, a5_0[0].y * w7p.y);
    out[g0 + 256] = fmaf(a5_1[0].x, w7p.x, a5_1[0].y * w7p.y);
}

extern "C" void kernel_launch(void* const* d_in, const int* in_sizes, int n_in,
                              void* d_out, int out_size) {
    const float* x  = (const float*)d_in[0];
    const float* w1 = (const float*)d_in[1];
    const float* w2 = (const float*)d_in[2];
    const float* w3 = (const float*)d_in[3];
    const float* w4 = (const float*)d_in[4];
    const float* w5 = (const float*)d_in[5];
    const float* w6 = (const float*)d_in[6];
    const float* w7 = (const float*)d_in[7];
    float* out = (float*)d_out;

    cudaFuncSetAttribute(fused_mlp7_hmma_kernel,
                         cudaFuncAttributeMaxDynamicSharedMemorySize, SMEM_TOTAL);
    fused_mlp7_hmma_kernel<<<NCTAS, THREADS, SMEM_TOTAL>>>(x, w1, w2, w3, w4, w5, w6, w7, out);
}